// round 1
// baseline (speedup 1.0000x reference)
#include <cuda_runtime.h>

// DIN attention layer, B=2048, L=200, E=128, H=64, fp32.
// Decomposition: attn_in@W1 = qa_b + k @ M_b with
//   qa_b[h] = b1[h] + sum_e q[e]*(W1[e][h] + W1[384+e][h])
//   M_b[e][h] = W1[128+e][h] - W1[384+e][h] + q[e]*W1[256+e][h]
// One CTA per batch row. Keys staged in smem. Packed fma.rn.f32x2 inner loops.

namespace {
constexpr int Bn = 2048;
constexpr int L  = 200;
constexpr int E  = 128;
constexpr int H  = 64;
constexpr int NT = 512;   // threads
constexpr int NW = 16;    // warps
constexpr int TILES = L / 8;  // 25 tiles of 8 keys

// shared memory layout (in floats)
constexpr int OFF_K    = 0;                   // keys tile           L*E   = 25600
constexpr int OFF_M    = OFF_K  + L * E;      // M_b                 E*H   = 8192
constexpr int OFF_W2   = OFF_M  + E * H;      // W2                  H*H   = 4096
constexpr int OFF_H    = OFF_W2 + H * H;      // per-warp h1 scratch NW*8*H= 8192
constexpr int OFF_Q    = OFF_H  + NW * 8 * H; // q                   E     = 128
constexpr int OFF_QA   = OFF_Q  + E;          // qa                  H
constexpr int OFF_W3   = OFF_QA + H;          // W3                  H
constexpr int OFF_B2   = OFF_W3 + H;          // b2                  H
constexpr int OFF_S    = OFF_B2 + H;          // scores/probs        208 (padded)
constexpr int OFF_MK   = OFF_S  + 208;        // mask (int view)     208
constexpr int OFF_RED  = OFF_MK + 208;        // reductions          32
constexpr int OFF_PART = OFF_RED + 32;        // weighted-sum parts  4*E = 512
constexpr int SMEM_FLOATS = OFF_PART + 4 * E; // = 47360 -> 189440 bytes
}

typedef unsigned long long ull;

__device__ __forceinline__ void ffma2(ull& d, ull a, ull b) {
    asm("fma.rn.f32x2 %0, %1, %2, %0;" : "+l"(d) : "l"(a), "l"(b));
}
__device__ __forceinline__ ull dup2(float x) {
    ull r;
    asm("mov.b64 %0, {%1, %1};" : "=l"(r) : "f"(x));
    return r;
}
__device__ __forceinline__ float2 upk(ull v) {
    float2 r;
    asm("mov.b64 {%0, %1}, %2;" : "=f"(r.x), "=f"(r.y) : "l"(v));
    return r;
}

__global__ __launch_bounds__(NT, 1)
void din_kernel(const float* __restrict__ query,
                const float* __restrict__ keys,
                const int*   __restrict__ mask,
                const float* __restrict__ W1,
                const float* __restrict__ b1,
                const float* __restrict__ W2,
                const float* __restrict__ b2,
                const float* __restrict__ W3,
                const float* __restrict__ b3,
                const float* __restrict__ nohist,
                float* __restrict__ out)
{
    extern __shared__ __align__(16) float sm[];
    float* sK   = sm + OFF_K;
    float* sM   = sm + OFF_M;
    float* sW2  = sm + OFF_W2;
    float* sHh  = sm + OFF_H;
    float* sQ   = sm + OFF_Q;
    float* sQa  = sm + OFF_QA;
    float* sW3  = sm + OFF_W3;
    float* sB2  = sm + OFF_B2;
    float* sS   = sm + OFF_S;
    int*   sMk  = reinterpret_cast<int*>(sm + OFF_MK);
    float* sRed = sm + OFF_RED;
    float* sPart= sm + OFF_PART;

    const int tid  = threadIdx.x;
    const int lane = tid & 31;
    const int warp = tid >> 5;
    const int b    = blockIdx.x;

    // ---------- stage inputs ----------
    const float* kb = keys + (size_t)b * (L * E);
    #pragma unroll 4
    for (int i = tid; i < (L * E) / 4; i += NT)
        reinterpret_cast<float4*>(sK)[i] = reinterpret_cast<const float4*>(kb)[i];
    for (int i = tid; i < (H * H) / 4; i += NT)
        reinterpret_cast<float4*>(sW2)[i] = reinterpret_cast<const float4*>(W2)[i];
    if (tid < E) sQ[tid] = query[b * E + tid];
    if (tid < H) { sW3[tid] = W3[tid]; sB2[tid] = b2[tid]; }
    if (tid < L) sMk[tid] = mask[b * L + tid];
    __syncthreads();

    // ---------- per-batch combined weights ----------
    for (int i = tid; i < E * H; i += NT) {
        const int e = i >> 6, h = i & (H - 1);
        sM[i] = W1[(128 + e) * H + h] - W1[(384 + e) * H + h]
              + sQ[e] * W1[(256 + e) * H + h];
    }
    if (tid < H) {
        float acc = b1[tid];
        #pragma unroll 4
        for (int e = 0; e < E; ++e)
            acc += sQ[e] * (W1[e * H + tid] + W1[(384 + e) * H + tid]);
        sQa[tid] = acc;
    }
    __syncthreads();

    const float b3v = b3[0];
    float* hrow = sHh + warp * (8 * H);

    // ---------- scorer: per-warp tiles of 8 keys ----------
    for (int tile = warp; tile < TILES; tile += NW) {
        const int l0 = tile * 8;
        const float* kbase = sK + l0 * E;

        // GEMM1: h1[8 x 64] = relu(qa + k @ M)
        ull acc[8];
        {
            const ull qa = *reinterpret_cast<const ull*>(sQa + 2 * lane);
            #pragma unroll
            for (int j = 0; j < 8; ++j) acc[j] = qa;
        }
        #pragma unroll 2
        for (int e4 = 0; e4 < E / 4; ++e4) {
            float4 kv[8];
            #pragma unroll
            for (int j = 0; j < 8; ++j)
                kv[j] = *reinterpret_cast<const float4*>(kbase + j * E + e4 * 4);
            #pragma unroll
            for (int t = 0; t < 4; ++t) {
                const int e = e4 * 4 + t;
                const ull m = *reinterpret_cast<const ull*>(sM + e * H + 2 * lane);
                #pragma unroll
                for (int j = 0; j < 8; ++j) {
                    const float kf = (t == 0) ? kv[j].x : (t == 1) ? kv[j].y
                                   : (t == 2) ? kv[j].z : kv[j].w;
                    ffma2(acc[j], dup2(kf), m);
                }
            }
        }
        __syncwarp();
        #pragma unroll
        for (int j = 0; j < 8; ++j) {
            const float2 a = upk(acc[j]);
            hrow[j * H + 2 * lane]     = fmaxf(a.x, 0.f);
            hrow[j * H + 2 * lane + 1] = fmaxf(a.y, 0.f);
        }
        __syncwarp();

        // GEMM2: h2 = relu(b2 + h1 @ W2)
        ull acc2[8];
        {
            const ull bb = *reinterpret_cast<const ull*>(sB2 + 2 * lane);
            #pragma unroll
            for (int j = 0; j < 8; ++j) acc2[j] = bb;
        }
        #pragma unroll 2
        for (int h4 = 0; h4 < H / 4; ++h4) {
            float4 hv[8];
            #pragma unroll
            for (int j = 0; j < 8; ++j)
                hv[j] = *reinterpret_cast<const float4*>(hrow + j * H + h4 * 4);
            #pragma unroll
            for (int t = 0; t < 4; ++t) {
                const int hh = h4 * 4 + t;
                const ull m = *reinterpret_cast<const ull*>(sW2 + hh * H + 2 * lane);
                #pragma unroll
                for (int j = 0; j < 8; ++j) {
                    const float hf = (t == 0) ? hv[j].x : (t == 1) ? hv[j].y
                                   : (t == 2) ? hv[j].z : hv[j].w;
                    ffma2(acc2[j], dup2(hf), m);
                }
            }
        }

        // layer 3: s = relu(h2) . W3 + b3  (warp butterfly reduce)
        const float w3x = sW3[2 * lane], w3y = sW3[2 * lane + 1];
        #pragma unroll
        for (int j = 0; j < 8; ++j) {
            const float2 a = upk(acc2[j]);
            float p = fmaxf(a.x, 0.f) * w3x + fmaxf(a.y, 0.f) * w3y;
            #pragma unroll
            for (int o = 16; o > 0; o >>= 1)
                p += __shfl_xor_sync(0xffffffffu, p, o);
            if (lane == j) sS[l0 + j] = p + b3v;
        }
        __syncwarp();
    }
    __syncthreads();

    // ---------- masked softmax over L ----------
    float vmax = -3.0e38f;
    if (tid < L && sMk[tid]) vmax = sS[tid];
    #pragma unroll
    for (int o = 16; o > 0; o >>= 1)
        vmax = fmaxf(vmax, __shfl_xor_sync(0xffffffffu, vmax, o));
    if (lane == 0) sRed[warp] = vmax;
    __syncthreads();
    if (warp == 0) {
        float v = (lane < NW) ? sRed[lane] : -3.0e38f;
        #pragma unroll
        for (int o = 16; o > 0; o >>= 1)
            v = fmaxf(v, __shfl_xor_sync(0xffffffffu, v, o));
        if (lane == 0) sRed[0] = v;
    }
    __syncthreads();
    const float smax = sRed[0];

    float p = 0.f, mc = 0.f;
    if (tid < L) {
        const int m = sMk[tid];
        p  = m ? __expf(sS[tid] - smax) : 0.f;
        mc = m ? 1.f : 0.f;
        sS[tid] = p;
    }
    float sp = p, sc = mc;
    #pragma unroll
    for (int o = 16; o > 0; o >>= 1) {
        sp += __shfl_xor_sync(0xffffffffu, sp, o);
        sc += __shfl_xor_sync(0xffffffffu, sc, o);
    }
    if (lane == 0) { sRed[warp] = sp; sRed[NW + warp] = sc; }
    __syncthreads();
    if (warp == 0) {
        float a = (lane < NW) ? sRed[lane] : 0.f;
        float c = (lane < NW) ? sRed[NW + lane] : 0.f;
        #pragma unroll
        for (int o = 16; o > 0; o >>= 1) {
            a += __shfl_xor_sync(0xffffffffu, a, o);
            c += __shfl_xor_sync(0xffffffffu, c, o);
        }
        if (lane == 0) { sRed[0] = a; sRed[1] = c; }
    }
    __syncthreads();
    const float denom  = sRed[0];
    const bool  allpad = (sRed[1] < 0.5f);
    const float inv    = allpad ? 0.f : (1.0f / denom);

    // ---------- weighted sum of keys ----------
    {
        const int e = tid & (E - 1);
        const int r = tid >> 7;          // 4 partitions of 50 keys each
        float acc = 0.f;
        const int lbeg = r * 50;
        #pragma unroll 5
        for (int l = lbeg; l < lbeg + 50; ++l)
            acc += sS[l] * sK[l * E + e];
        sPart[r * E + e] = acc;
    }
    __syncthreads();
    if (tid < E) {
        float o = (sPart[tid] + sPart[E + tid] + sPart[2 * E + tid] + sPart[3 * E + tid]) * inv;
        if (allpad) o = nohist[tid];
        out[b * E + tid] = o;
    }
}

extern "C" void kernel_launch(void* const* d_in, const int* in_sizes, int n_in,
                              void* d_out, int out_size) {
    const float* query = (const float*)d_in[0];
    const float* keys  = (const float*)d_in[1];
    const int*   mask  = (const int*)  d_in[2];
    const float* W1    = (const float*)d_in[3];
    const float* b1    = (const float*)d_in[4];
    const float* W2    = (const float*)d_in[5];
    const float* b2    = (const float*)d_in[6];
    const float* W3    = (const float*)d_in[7];
    const float* b3    = (const float*)d_in[8];
    const float* nh    = (const float*)d_in[9];
    float* out = (float*)d_out;

    cudaFuncSetAttribute(din_kernel, cudaFuncAttributeMaxDynamicSharedMemorySize,
                         SMEM_FLOATS * (int)sizeof(float));
    din_kernel<<<Bn, NT, SMEM_FLOATS * sizeof(float)>>>(
        query, keys, mask, W1, b1, W2, b2, W3, b3, nh, out);
}

// round 2
// speedup vs baseline: 1.0804x; 1.0804x over previous
#include <cuda_runtime.h>

// DIN attention layer, B=2048, L=200, E=128, H=64, fp32.
// Decomposition: attn_in@W1 = qa_b + k @ M_b with
//   qa_b[h] = b1[h] + sum_e q[e]*(W1[e][h] + W1[384+e][h])
//   M_b[e][h] = W1[128+e][h] - W1[384+e][h] + q[e]*W1[256+e][h]
// One CTA per batch. 20 warps, each scores exactly one 10-key tile.
// f32x2 FMAs vectorized over KEY pairs (no per-FMA dup movs):
// keys staged transposed kT[e][tile][10], h1 staged transposed h1T[h][j].

namespace {
constexpr int Bn = 2048;
constexpr int L  = 200;
constexpr int E  = 128;
constexpr int H  = 64;
constexpr int NT = 640;   // threads
constexpr int NW = 20;    // warps
constexpr int TK = 10;    // keys per tile (= per warp)
constexpr int LS = 244;   // kT row stride (floats): 20 tiles * 12 + pad
constexpr int TS = 12;    // per-tile stride within kT row

// shared memory layout (floats)
constexpr int OFF_KT  = 0;                     // 128*244 = 31232
constexpr int OFF_M   = OFF_KT + E * LS;       // 8192
constexpr int OFF_W2  = OFF_M  + E * H;        // 4096
constexpr int OFF_H   = OFF_W2 + H * H;        // 20 * 640 = 12800 (h1T per warp)
constexpr int OFF_Q   = OFF_H  + NW * H * TK;  // 128
constexpr int OFF_QA  = OFF_Q  + E;            // 64
constexpr int OFF_W3  = OFF_QA + H;            // 64
constexpr int OFF_B2  = OFF_W3 + H;            // 64
constexpr int OFF_S   = OFF_B2 + H;            // 208
constexpr int OFF_MK  = OFF_S  + 208;          // 208
constexpr int OFF_RED = OFF_MK + 208;          // 64
constexpr int OFF_PART= OFF_RED + 64;          // 640 (also qa partials)
constexpr int SMEM_FLOATS = OFF_PART + NT;     // 57760 floats = 231040 B
}

typedef unsigned long long ull;

__device__ __forceinline__ void ffma2(ull& d, ull a, ull b) {
    asm("fma.rn.f32x2 %0, %1, %2, %0;" : "+l"(d) : "l"(a), "l"(b));
}
__device__ __forceinline__ ull dup2(float x) {
    ull r;
    asm("mov.b64 %0, {%1, %1};" : "=l"(r) : "f"(x));
    return r;
}
__device__ __forceinline__ float2 upk(ull v) {
    float2 r;
    asm("mov.b64 {%0, %1}, %2;" : "=f"(r.x), "=f"(r.y) : "l"(v));
    return r;
}

__global__ __launch_bounds__(NT, 1)
void din_kernel(const float* __restrict__ query,
                const float* __restrict__ keys,
                const int*   __restrict__ mask,
                const float* __restrict__ W1,
                const float* __restrict__ b1,
                const float* __restrict__ W2,
                const float* __restrict__ b2,
                const float* __restrict__ W3,
                const float* __restrict__ b3,
                const float* __restrict__ nohist,
                float* __restrict__ out)
{
    extern __shared__ __align__(16) float sm[];
    float* sKT  = sm + OFF_KT;
    float* sM   = sm + OFF_M;
    float* sW2  = sm + OFF_W2;
    float* sH   = sm + OFF_H;
    float* sQ   = sm + OFF_Q;
    float* sQa  = sm + OFF_QA;
    float* sW3  = sm + OFF_W3;
    float* sB2  = sm + OFF_B2;
    float* sS   = sm + OFF_S;
    int*   sMk  = reinterpret_cast<int*>(sm + OFF_MK);
    float* sRed = sm + OFF_RED;
    float* sPart= sm + OFF_PART;

    const int tid  = threadIdx.x;
    const int lane = tid & 31;
    const int warp = tid >> 5;
    const int b    = blockIdx.x;

    // ---------- stage: transpose keys into kT[e][t*12 + jj] ----------
    {
        const float4* kb4 = reinterpret_cast<const float4*>(keys + (size_t)b * (L * E));
        #pragma unroll
        for (int it = 0; it < 10; ++it) {
            const int j  = it * NT + tid;        // 0..6399
            const int e4 = j / 200;              // 0..31
            const int lp = j - e4 * 200;         // 0..199
            const float4 v = kb4[lp * 32 + e4];
            const int t  = lp / 10;
            const int jj = lp - t * 10;
            float* dst = sKT + (4 * e4) * LS + t * TS + jj;
            dst[0]      = v.x;
            dst[LS]     = v.y;
            dst[2 * LS] = v.z;
            dst[3 * LS] = v.w;
        }
    }
    for (int i = tid; i < (H * H) / 4; i += NT)
        reinterpret_cast<float4*>(sW2)[i] = reinterpret_cast<const float4*>(W2)[i];
    if (tid < E) sQ[tid] = query[b * E + tid];
    if (tid < H) { sW3[tid] = W3[tid]; sB2[tid] = b2[tid]; }
    if (tid < L) sMk[tid] = mask[b * L + tid];
    __syncthreads();

    // ---------- per-batch combined weights ----------
    for (int i = tid; i < E * H; i += NT) {
        const int e = i >> 6, h = i & (H - 1);
        sM[i] = W1[(128 + e) * H + h] - W1[(384 + e) * H + h]
              + sQ[e] * W1[(256 + e) * H + h];
    }
    {   // qa partials: 10 e-chunks x 64 h
        const int h = tid & (H - 1);
        const int r = tid >> 6;                  // 0..9
        const int e0 = r * 13;
        const int e1 = (e0 + 13 < E) ? e0 + 13 : E;
        float acc = 0.f;
        for (int e = e0; e < e1; ++e)
            acc += sQ[e] * (W1[e * H + h] + W1[(384 + e) * H + h]);
        sPart[r * H + h] = acc;
    }
    __syncthreads();
    if (tid < H) {
        float acc = b1[tid];
        #pragma unroll
        for (int r = 0; r < 10; ++r) acc += sPart[r * H + tid];
        sQa[tid] = acc;
    }
    __syncthreads();

    // ---------- scorer: each warp does one tile of 10 keys ----------
    {
        const int t  = warp;
        const int l0 = t * TK;
        const float* kTt = sKT + t * TS;
        const float* mrow = sM + 2 * lane;

        ull acc[5][2];                 // [jpair][h_local], h = 2*lane + hl
        #pragma unroll
        for (int jp = 0; jp < 5; ++jp) { acc[jp][0] = 0ull; acc[jp][1] = 0ull; }

        #pragma unroll 2
        for (int e = 0; e < E; ++e) {
            const float* kr = kTt + e * LS;
            const ulonglong2 kA = *reinterpret_cast<const ulonglong2*>(kr);     // j0..3
            const ull        kC = *reinterpret_cast<const ull*>(kr + 4 + 4);    // j8,9
            const ulonglong2 kB = *reinterpret_cast<const ulonglong2*>(kr + 4); // j4..7
            const float2 m2 = *reinterpret_cast<const float2*>(mrow + e * H);
            const ull ma = dup2(m2.x);
            const ull mb = dup2(m2.y);
            ffma2(acc[0][0], kA.x, ma); ffma2(acc[0][1], kA.x, mb);
            ffma2(acc[1][0], kA.y, ma); ffma2(acc[1][1], kA.y, mb);
            ffma2(acc[2][0], kB.x, ma); ffma2(acc[2][1], kB.x, mb);
            ffma2(acc[3][0], kB.y, ma); ffma2(acc[3][1], kB.y, mb);
            ffma2(acc[4][0], kC,   ma); ffma2(acc[4][1], kC,   mb);
        }

        // h1T[h][j] = relu(qa[h] + acc), per-warp scratch, row stride 10
        float* hT = sH + warp * (H * TK);
        const float qax = sQa[2 * lane], qay = sQa[2 * lane + 1];
        #pragma unroll
        for (int jp = 0; jp < 5; ++jp) {
            const float2 a0 = upk(acc[jp][0]);   // h = 2*lane
            const float2 a1 = upk(acc[jp][1]);   // h = 2*lane+1
            *reinterpret_cast<float2*>(hT + (2 * lane) * TK + 2 * jp) =
                make_float2(fmaxf(a0.x + qax, 0.f), fmaxf(a0.y + qax, 0.f));
            *reinterpret_cast<float2*>(hT + (2 * lane + 1) * TK + 2 * jp) =
                make_float2(fmaxf(a1.x + qay, 0.f), fmaxf(a1.y + qay, 0.f));
        }
        __syncwarp();

        // GEMM2: h2[j][h'] = sum_h h1[j][h] * W2[h][h']   (bias folded later)
        ull acc2[5][2];
        #pragma unroll
        for (int jp = 0; jp < 5; ++jp) { acc2[jp][0] = 0ull; acc2[jp][1] = 0ull; }

        #pragma unroll 2
        for (int h = 0; h < H; ++h) {
            const float* hrow = hT + h * TK;
            const ull h01 = *reinterpret_cast<const ull*>(hrow);
            const ull h23 = *reinterpret_cast<const ull*>(hrow + 2);
            const ull h45 = *reinterpret_cast<const ull*>(hrow + 4);
            const ull h67 = *reinterpret_cast<const ull*>(hrow + 6);
            const ull h89 = *reinterpret_cast<const ull*>(hrow + 8);
            const float2 w2 = *reinterpret_cast<const float2*>(sW2 + h * H + 2 * lane);
            const ull wa = dup2(w2.x);
            const ull wb = dup2(w2.y);
            ffma2(acc2[0][0], h01, wa); ffma2(acc2[0][1], h01, wb);
            ffma2(acc2[1][0], h23, wa); ffma2(acc2[1][1], h23, wb);
            ffma2(acc2[2][0], h45, wa); ffma2(acc2[2][1], h45, wb);
            ffma2(acc2[3][0], h67, wa); ffma2(acc2[3][1], h67, wb);
            ffma2(acc2[4][0], h89, wa); ffma2(acc2[4][1], h89, wb);
        }

        // layer 3: s[j] = relu(h2[j]+b2) . W3 + b3 via warp butterfly
        const float w3x = sW3[2 * lane], w3y = sW3[2 * lane + 1];
        const float b2x = sB2[2 * lane], b2y = sB2[2 * lane + 1];
        const float b3v = b3[0];
        #pragma unroll
        for (int jp = 0; jp < 5; ++jp) {
            const float2 a0 = upk(acc2[jp][0]);  // h' = 2*lane   : (j=2jp, j=2jp+1)
            const float2 a1 = upk(acc2[jp][1]);  // h' = 2*lane+1
            float pa = fmaxf(a0.x + b2x, 0.f) * w3x + fmaxf(a1.x + b2y, 0.f) * w3y;
            float pb = fmaxf(a0.y + b2x, 0.f) * w3x + fmaxf(a1.y + b2y, 0.f) * w3y;
            #pragma unroll
            for (int o = 16; o > 0; o >>= 1) {
                pa += __shfl_xor_sync(0xffffffffu, pa, o);
                pb += __shfl_xor_sync(0xffffffffu, pb, o);
            }
            if (lane == 0) {
                sS[l0 + 2 * jp]     = pa + b3v;
                sS[l0 + 2 * jp + 1] = pb + b3v;
            }
        }
    }
    __syncthreads();

    // ---------- masked softmax over L ----------
    float vmax = -3.0e38f;
    if (tid < L && sMk[tid]) vmax = sS[tid];
    #pragma unroll
    for (int o = 16; o > 0; o >>= 1)
        vmax = fmaxf(vmax, __shfl_xor_sync(0xffffffffu, vmax, o));
    if (lane == 0) sRed[warp] = vmax;
    __syncthreads();
    if (warp == 0) {
        float v = (lane < NW) ? sRed[lane] : -3.0e38f;
        #pragma unroll
        for (int o = 16; o > 0; o >>= 1)
            v = fmaxf(v, __shfl_xor_sync(0xffffffffu, v, o));
        if (lane == 0) sRed[0] = v;
    }
    __syncthreads();
    const float smax = sRed[0];

    float p = 0.f, mc = 0.f;
    if (tid < L) {
        const int m = sMk[tid];
        p  = m ? __expf(sS[tid] - smax) : 0.f;
        mc = m ? 1.f : 0.f;
        sS[tid] = p;
    }
    float sp = p, sc = mc;
    #pragma unroll
    for (int o = 16; o > 0; o >>= 1) {
        sp += __shfl_xor_sync(0xffffffffu, sp, o);
        sc += __shfl_xor_sync(0xffffffffu, sc, o);
    }
    if (lane == 0) { sRed[warp] = sp; sRed[NW + warp] = sc; }
    __syncthreads();
    if (warp == 0) {
        float a = (lane < NW) ? sRed[lane] : 0.f;
        float c = (lane < NW) ? sRed[NW + lane] : 0.f;
        #pragma unroll
        for (int o = 16; o > 0; o >>= 1) {
            a += __shfl_xor_sync(0xffffffffu, a, o);
            c += __shfl_xor_sync(0xffffffffu, c, o);
        }
        if (lane == 0) { sRed[0] = a; sRed[1] = c; }
    }
    __syncthreads();
    const float denom  = sRed[0];
    const bool  allpad = (sRed[1] < 0.5f);
    const float inv    = allpad ? 0.f : (1.0f / denom);

    // ---------- weighted sum of keys (from kT) ----------
    {
        const int e = tid & (E - 1);
        const int r = tid >> 7;                  // 0..4, 4 tiles each
        float acc = 0.f;
        #pragma unroll
        for (int t2 = 0; t2 < 4; ++t2) {
            const int t = r * 4 + t2;
            const float* kbs = sKT + e * LS + t * TS;
            const float* pbs = sS + t * TK;
            #pragma unroll
            for (int jj = 0; jj < 5; ++jj) {
                const float2 kv = *reinterpret_cast<const float2*>(kbs + 2 * jj);
                const float2 pv = *reinterpret_cast<const float2*>(pbs + 2 * jj);
                acc += pv.x * kv.x + pv.y * kv.y;
            }
        }
        sPart[r * E + e] = acc;
    }
    __syncthreads();
    if (tid < E) {
        float o = (sPart[tid] + sPart[E + tid] + sPart[2 * E + tid]
                 + sPart[3 * E + tid] + sPart[4 * E + tid]) * inv;
        if (allpad) o = nohist[tid];
        out[b * E + tid] = o;
    }
}

extern "C" void kernel_launch(void* const* d_in, const int* in_sizes, int n_in,
                              void* d_out, int out_size) {
    const float* query = (const float*)d_in[0];
    const float* keys  = (const float*)d_in[1];
    const int*   mask  = (const int*)  d_in[2];
    const float* W1    = (const float*)d_in[3];
    const float* b1    = (const float*)d_in[4];
    const float* W2    = (const float*)d_in[5];
    const float* b2    = (const float*)d_in[6];
    const float* W3    = (const float*)d_in[7];
    const float* b3    = (const float*)d_in[8];
    const float* nh    = (const float*)d_in[9];
    float* out = (float*)d_out;

    cudaFuncSetAttribute(din_kernel, cudaFuncAttributeMaxDynamicSharedMemorySize,
                         SMEM_FLOATS * (int)sizeof(float));
    din_kernel<<<Bn, NT, SMEM_FLOATS * sizeof(float)>>>(
        query, keys, mask, W1, b1, W2, b2, W3, b3, nh, out);
}